// round 7
// baseline (speedup 1.0000x reference)
#include <cuda_runtime.h>
#include <cuda_bf16.h>
#include <cstdint>

#define DEV __device__ __forceinline__

constexpr int Bn    = 65536;   // batch
constexpr int Hh    = 64;      // hidden
constexpr int Gg    = 192;     // 3*H
constexpr int Kf    = 1024;    // T*H
constexpr int Tt    = 16;      // type count
constexpr int TILES = 17;      // 16 register tiles + 1 c tile (64 k each)
constexpr int WTILE_BYTES = Gg * 128;   // 192 rows x 128B (64 bf16) = 24576

// ---- device-global scratch (no allocations allowed) ----
__device__ float g_hidden[(size_t)Bn * Hh];                        // stage A output
__device__ __align__(16) unsigned char g_Whi[TILES * WTILE_BYTES]; // bf16 hi, tile-swizzled
__device__ __align__(16) unsigned char g_Wlo[TILES * WTILE_BYTES]; // bf16 lo, tile-swizzled

// single dynamic shared memory declaration shared by all kernels
extern __shared__ __align__(1024) char dynsm[];

DEV float sigm(float v) { return 1.0f / (1.0f + __expf(-v)); }

DEV uint32_t smem_u32(const void* p) {
    uint32_t a;
    asm("{ .reg .u64 t; cvta.to.shared.u64 t, %1; cvt.u32.u64 %0, t; }" : "=r"(a) : "l"(p));
    return a;
}
DEV uint32_t sw128(uint32_t off) { return off ^ ((off >> 3) & 0x70); }

DEV void ldsm4(uint32_t* r, uint32_t addr) {
    asm volatile("ldmatrix.sync.aligned.m8n8.x4.shared.b16 {%0,%1,%2,%3}, [%4];"
        : "=r"(r[0]), "=r"(r[1]), "=r"(r[2]), "=r"(r[3]) : "r"(addr));
}
DEV void mma_bf16(float* d, const uint32_t* a, const uint32_t* b) {
    asm volatile(
        "mma.sync.aligned.m16n8k16.row.col.f32.bf16.bf16.f32 "
        "{%0,%1,%2,%3}, {%4,%5,%6,%7}, {%8,%9}, {%0,%1,%2,%3};"
        : "+f"(d[0]), "+f"(d[1]), "+f"(d[2]), "+f"(d[3])
        : "r"(a[0]), "r"(a[1]), "r"(a[2]), "r"(a[3]), "r"(b[0]), "r"(b[1]));
}
DEV void cp16(uint32_t smem, const void* g) {
    asm volatile("cp.async.cg.shared.global [%0], [%1], 16;" :: "r"(smem), "l"(g));
}
DEV void cp_commit() { asm volatile("cp.async.commit_group;" ::: "memory"); }
DEV void cp_wait0()  { asm volatile("cp.async.wait_group 0;" ::: "memory"); }

// ---------------------------------------------------------------------------
// buildW: split core weights into bf16 hi/lo, stored per-64k-tile in the exact
// SW128 smem layout (so the GEMM's W load is a raw cp.async copy).
// Wt[g][k] = cWih[g][k] (k<1024) else cWhh[g][k-1024]; tile t covers k=t*64..
// ---------------------------------------------------------------------------
__global__ void buildW_kernel(const float* __restrict__ cWih, const float* __restrict__ cWhh) {
    int idx = blockIdx.x * 256 + threadIdx.x;
    if (idx >= TILES * Gg * 64) return;
    int t   = idx / (Gg * 64);
    int rem = idx - t * (Gg * 64);
    int r   = rem >> 6;          // gate row 0..191
    int kk  = rem & 63;
    int k   = t * 64 + kk;
    float val = (k < Kf) ? cWih[(size_t)r * Kf + k] : cWhh[r * Hh + (k - Kf)];
    __nv_bfloat16 hi = __float2bfloat16(val);
    __nv_bfloat16 lo = __float2bfloat16(val - __bfloat162float(hi));
    uint32_t off = sw128((uint32_t)(r * 128 + kk * 2));
    *(__nv_bfloat16*)(g_Whi + (size_t)t * WTILE_BYTES + off) = hi;
    *(__nv_bfloat16*)(g_Wlo + (size_t)t * WTILE_BYTES + off) = lo;
}

// ---------------------------------------------------------------------------
// Stage A: per-(type, chunk) block. Compact matching rows, run the per-type
// GRU (gi = Wih@x + bih, gh = Whh@reg + bhh) -> g_hidden.
// ---------------------------------------------------------------------------
constexpr int SMEMA_BYTES = (64 * Gg * 2 + 2048 * 2 + 1024 + 8) * 4;

__global__ void __launch_bounds__(256, 1)
stageA_kernel(const float* __restrict__ x, const int* __restrict__ typ,
              const float* __restrict__ regs,
              const float* __restrict__ Wih, const float* __restrict__ Whh,
              const float* __restrict__ bih, const float* __restrict__ bhh)
{
    float* sm = (float*)dynsm;
    float* WI = sm;
    float* WH = WI + 64 * Gg;
    float* xs = WH + 64 * Gg;
    float* rs = xs + 2048;
    int*  list = (int*)(rs + 2048);
    int*  pcnt = list + 1024;

    const int tid = threadIdx.x;
    const int t   = blockIdx.y;
    const int c0  = blockIdx.x * 1024;

    if (tid == 0) *pcnt = 0;
    __syncthreads();
    for (int i = tid; i < 1024; i += 256) {
        if (typ[c0 + i] == t) list[atomicAdd(pcnt, 1)] = c0 + i;
    }
    __syncthreads();
    const int n = *pcnt;
    if (n == 0) return;

    if (tid < Gg) {
        const float* wi = Wih + ((size_t)t * Gg + tid) * 64;
        const float* wh = Whh + ((size_t)t * Gg + tid) * 64;
        #pragma unroll
        for (int q = 0; q < 16; q++) {
            float4 a = *(const float4*)(wi + q * 4);
            WI[(q*4+0)*Gg + tid] = a.x; WI[(q*4+1)*Gg + tid] = a.y;
            WI[(q*4+2)*Gg + tid] = a.z; WI[(q*4+3)*Gg + tid] = a.w;
            float4 b = *(const float4*)(wh + q * 4);
            WH[(q*4+0)*Gg + tid] = b.x; WH[(q*4+1)*Gg + tid] = b.y;
            WH[(q*4+2)*Gg + tid] = b.z; WH[(q*4+3)*Gg + tid] = b.w;
        }
    }
    __syncthreads();

    const int w = tid >> 5, l = tid & 31;
    const float* bip = bih + t * Gg + 2 * l;
    const float* bhp = bhh + t * Gg + 2 * l;
    const float2 bI0 = *(const float2*)(bip),      bI1 = *(const float2*)(bip + 64),
                 bI2 = *(const float2*)(bip + 128);
    const float2 bH0 = *(const float2*)(bhp),      bH1 = *(const float2*)(bhp + 64),
                 bH2 = *(const float2*)(bhp + 128);
    float* xw = xs + w * 256;
    float* rw = rs + w * 256;

    for (int base = w * 4; base < n; base += 32) {
        int bi4[4];
        #pragma unroll
        for (int i = 0; i < 4; i++) {
            int j = base + i; if (j > n - 1) j = n - 1;
            bi4[i] = list[j];
        }
        #pragma unroll
        for (int i = 0; i < 4; i++) {
            *(float2*)(xw + i * 64 + 2 * l) = *(const float2*)(x    + (size_t)bi4[i] * 64 + 2 * l);
            *(float2*)(rw + i * 64 + 2 * l) = *(const float2*)(regs + (size_t)bi4[i] * Kf + t * 64 + 2 * l);
        }
        __syncwarp();

        float2 gi0[4], gi1[4], gi2[4], gh0[4], gh1[4], gh2[4];
        #pragma unroll
        for (int i = 0; i < 4; i++) {
            gi0[i] = bI0; gi1[i] = bI1; gi2[i] = bI2;
            gh0[i] = bH0; gh1[i] = bH1; gh2[i] = bH2;
        }

        #pragma unroll 4
        for (int k = 0; k < 64; k++) {
            const float* wk = WI + k * Gg + 2 * l;
            float2 wi0 = *(const float2*)(wk),       wi1 = *(const float2*)(wk + 64),
                   wi2 = *(const float2*)(wk + 128);
            const float* hk = WH + k * Gg + 2 * l;
            float2 wh0 = *(const float2*)(hk),       wh1 = *(const float2*)(hk + 64),
                   wh2 = *(const float2*)(hk + 128);
            #pragma unroll
            for (int i = 0; i < 4; i++) {
                float xv = xw[i * 64 + k];
                float rv = rw[i * 64 + k];
                gi0[i].x = fmaf(wi0.x, xv, gi0[i].x); gi0[i].y = fmaf(wi0.y, xv, gi0[i].y);
                gi1[i].x = fmaf(wi1.x, xv, gi1[i].x); gi1[i].y = fmaf(wi1.y, xv, gi1[i].y);
                gi2[i].x = fmaf(wi2.x, xv, gi2[i].x); gi2[i].y = fmaf(wi2.y, xv, gi2[i].y);
                gh0[i].x = fmaf(wh0.x, rv, gh0[i].x); gh0[i].y = fmaf(wh0.y, rv, gh0[i].y);
                gh1[i].x = fmaf(wh1.x, rv, gh1[i].x); gh1[i].y = fmaf(wh1.y, rv, gh1[i].y);
                gh2[i].x = fmaf(wh2.x, rv, gh2[i].x); gh2[i].y = fmaf(wh2.y, rv, gh2[i].y);
            }
        }

        #pragma unroll
        for (int i = 0; i < 4; i++) {
            if (base + i < n) {
                float2 hv = *(const float2*)(rw + i * 64 + 2 * l);
                float r0 = sigm(gi0[i].x + gh0[i].x);
                float z0 = sigm(gi1[i].x + gh1[i].x);
                float n0 = tanhf(gi2[i].x + r0 * gh2[i].x);
                float o0 = (1.0f - z0) * n0 + z0 * hv.x;
                float r1 = sigm(gi0[i].y + gh0[i].y);
                float z1 = sigm(gi1[i].y + gh1[i].y);
                float n1 = tanhf(gi2[i].y + r1 * gh2[i].y);
                float o1 = (1.0f - z1) * n1 + z1 * hv.y;
                *(float2*)(g_hidden + (size_t)bi4[i] * 64 + 2 * l) = make_float2(o0, o1);
            }
        }
        __syncwarp();
    }
}

// ---------------------------------------------------------------------------
// Stage B: warp-level mma.sync bf16 GEMM, M=65536, N=192, K=17x64.
// Tile order: c-tile (t=16) FIRST -> snapshot hn (n-gate cols) to smem ->
// keep accumulating register tiles 0..15 into the same accumulators.
// Epilogue: n_pre = acc_n + (r-1)*hn_snap; fused GRU.
// ---------------------------------------------------------------------------
constexpr int SB_PIPE = 1024;
constexpr int STAGE   = 81920;                 // Ahi 16K | Alo 16K | Whi 24K | Wlo 24K
constexpr int SB_HN   = SB_PIPE + 2 * STAGE;   // 164864
constexpr int SMEMB_BYTES = SB_HN + 128 * 64 * 4;   // 197632

__global__ void __launch_bounds__(256, 1)
stageB_mma(const float* __restrict__ regs, const int* __restrict__ typ,
           const float* __restrict__ c,
           const float* __restrict__ cbih, const float* __restrict__ cbhh,
           float* __restrict__ out)
{
    char* sm = dynsm;
    const uint32_t sb = smem_u32(sm);
    const int tid  = threadIdx.x;
    const int wid  = tid >> 5, lane = tid & 31;
    const int wm   = wid & 3;      // m block: rows wm*32
    const int wn   = wid >> 2;     // n block: cols wn*96
    const int bm   = blockIdx.x * 128;

    int* styp = (int*)sm;          // [0,512)
    if (tid < 128) styp[tid] = typ[bm + tid];
    __syncthreads();

    float acc[2][12][4];
    #pragma unroll
    for (int a = 0; a < 2; a++)
        #pragma unroll
        for (int b = 0; b < 12; b++)
            #pragma unroll
            for (int r = 0; r < 4; r++) acc[a][b][r] = 0.0f;

    // ---- loaders ----
    auto loadW = [&](int t, int buf) {
        uint32_t wh = sb + SB_PIPE + buf * STAGE + 32768;
        uint32_t wl = wh + 24576;
        const unsigned char* sh = g_Whi + (size_t)t * WTILE_BYTES;
        const unsigned char* sl = g_Wlo + (size_t)t * WTILE_BYTES;
        #pragma unroll
        for (int j = 0; j < 6; j++) {
            int i = (tid + j * 256) * 16;
            cp16(wh + i, sh + i);
            cp16(wl + i, sl + i);
        }
    };
    auto loadA = [&](int t, int buf) {
        char* ah = sm + SB_PIPE + buf * STAGE;
        char* al = ah + 16384;
        #pragma unroll
        for (int j = 0; j < 16; j++) {
            int i   = tid + j * 256;
            int row = i >> 5;
            int pr  = i & 31;
            const float* srow;
            if (t < Tt) {
                srow = (styp[row] == t)
                         ? (g_hidden + (size_t)(bm + row) * 64)
                         : (regs + (size_t)(bm + row) * Kf + t * 64);
            } else {
                srow = c + (size_t)(bm + row) * 64;
            }
            float2 v = *(const float2*)(srow + pr * 2);
            __nv_bfloat16 h0 = __float2bfloat16(v.x);
            __nv_bfloat16 h1 = __float2bfloat16(v.y);
            __nv_bfloat16 l0 = __float2bfloat16(v.x - __bfloat162float(h0));
            __nv_bfloat16 l1 = __float2bfloat16(v.y - __bfloat162float(h1));
            uint32_t hb = ((uint32_t)__bfloat16_as_ushort(h1) << 16) | __bfloat16_as_ushort(h0);
            uint32_t lb = ((uint32_t)__bfloat16_as_ushort(l1) << 16) | __bfloat16_as_ushort(l0);
            uint32_t off = sw128((uint32_t)(row * 128 + pr * 4));
            *(uint32_t*)(ah + off) = hb;
            *(uint32_t*)(al + off) = lb;
        }
    };

    const int l8 = lane & 7, li = lane >> 3;
    const int am_off = (li & 1) * 8, ak_off = (li >> 1) * 8;
    const int wn_off = (li >> 1) * 8, wk_off = (li & 1) * 8;

    auto compute = [&](int buf) {
        const uint32_t a0 = sb + SB_PIPE + buf * STAGE;
        #pragma unroll
        for (int ks = 0; ks < 4; ks++) {
            const int k0 = ks * 16;
            uint32_t ah[2][4], al[2][4];
            #pragma unroll
            for (int mt = 0; mt < 2; mt++) {
                int row = wm * 32 + mt * 16 + am_off + l8;
                uint32_t off = sw128((uint32_t)(row * 128 + (k0 + ak_off) * 2));
                ldsm4(ah[mt], a0 + off);
                ldsm4(al[mt], a0 + 16384 + off);
            }
            #pragma unroll
            for (int np = 0; np < 6; np++) {
                int nrow = wn * 96 + np * 16 + wn_off + l8;
                uint32_t woff = sw128((uint32_t)(nrow * 128 + (k0 + wk_off) * 2));
                uint32_t whf[4], wlf[4];
                ldsm4(whf, a0 + 32768 + woff);
                ldsm4(wlf, a0 + 57344 + woff);
                #pragma unroll
                for (int mt = 0; mt < 2; mt++) {
                    mma_bf16(acc[mt][2*np],   ah[mt], whf);
                    mma_bf16(acc[mt][2*np+1], ah[mt], whf + 2);
                    mma_bf16(acc[mt][2*np],   ah[mt], wlf);
                    mma_bf16(acc[mt][2*np+1], ah[mt], wlf + 2);
                    mma_bf16(acc[mt][2*np],   al[mt], whf);
                    mma_bf16(acc[mt][2*np+1], al[mt], whf + 2);
                }
            }
        }
    };

    // ---- prologue: c-tile (t=16) into buf 0 ----
    loadW(16, 0);
    cp_commit();
    loadA(16, 0);
    cp_wait0();
    __syncthreads();

    // tile order: it=0 -> t=16 (c), it=1..16 -> t=it-1
    for (int it = 0; it <= 16; it++) {
        const int buf = it & 1, nxt = buf ^ 1;
        if (it < 16) { loadW(it, nxt); cp_commit(); }
        compute(buf);
        if (it == 0 && wn == 1) {
            // snapshot hn = (c @ cWhh_n^T) for the n-gate columns (128..191)
            float* Hn = (float*)(sm + SB_HN);
            #pragma unroll
            for (int mt = 0; mt < 2; mt++)
                #pragma unroll
                for (int nt = 4; nt < 12; nt++)
                    #pragma unroll
                    for (int r = 0; r < 4; r++) {
                        int row = wm * 32 + mt * 16 + (lane >> 2) + ((r >> 1) << 3);
                        int col = nt * 8 - 32 + ((lane & 3) << 1) + (r & 1);
                        Hn[row * 64 + col] = acc[mt][nt][r];
                    }
        }
        if (it < 16) { loadA(it, nxt); cp_wait0(); }
        __syncthreads();
    }

    // ---- epilogue ----
    float* Ds = (float*)(sm + SB_PIPE);               // [128][200]
    float* cs = (float*)(sm + SB_PIPE + 102400);      // [128][68]
    float* Hn = (float*)(sm + SB_HN);                 // [128][64]

    #pragma unroll
    for (int mt = 0; mt < 2; mt++)
        #pragma unroll
        for (int nt = 0; nt < 12; nt++)
            #pragma unroll
            for (int r = 0; r < 4; r++) {
                int row = wm * 32 + mt * 16 + (lane >> 2) + ((r >> 1) << 3);
                int col = wn * 96 + nt * 8 + ((lane & 3) << 1) + (r & 1);
                Ds[row * 200 + col] = acc[mt][nt][r];
            }
    #pragma unroll
    for (int j = 0; j < 8; j++) {
        int i   = tid + j * 256;
        int row = i >> 4, q = i & 15;
        float4 v = *(const float4*)(c + (size_t)(bm + row) * 64 + q * 4);
        *(float4*)(cs + row * 68 + q * 4) = v;
    }
    __syncthreads();

    const int h  = tid & 63;
    const int rl = tid >> 6;
    const float bR  = cbih[h]       + cbhh[h];
    const float bZ  = cbih[64 + h]  + cbhh[64 + h];
    const float bN  = cbih[128 + h];
    const float bHN = cbhh[128 + h];
    #pragma unroll 4
    for (int i = 0; i < 32; i++) {
        int row = rl + i * 4;
        float ar = Ds[row * 200 + h];
        float az = Ds[row * 200 + 64 + h];
        float an = Ds[row * 200 + 128 + h];
        float hn = Hn[row * 64 + h];
        float cv = cs[row * 68 + h];
        float rv = sigm(ar + bR);
        float zv = sigm(az + bZ);
        float nv = tanhf(an + bN + rv * bHN + (rv - 1.0f) * hn);
        out[(size_t)(bm + row) * 64 + h] = (1.0f - zv) * nv + zv * cv;
    }
}

// ---------------------------------------------------------------------------
extern "C" void kernel_launch(void* const* d_in, const int* in_sizes, int n_in,
                              void* d_out, int out_size)
{
    const float* x    = (const float*)d_in[0];
    const int*   typ  = (const int*)  d_in[1];
    const float* c    = (const float*)d_in[2];
    const float* regs = (const float*)d_in[3];
    const float* Wih  = (const float*)d_in[4];
    const float* Whh  = (const float*)d_in[5];
    const float* bih  = (const float*)d_in[6];
    const float* bhh  = (const float*)d_in[7];
    const float* cWih = (const float*)d_in[8];
    const float* cWhh = (const float*)d_in[9];
    const float* cbih = (const float*)d_in[10];
    const float* cbhh = (const float*)d_in[11];
    float* out = (float*)d_out;

    (void)in_sizes; (void)n_in; (void)out_size;

    cudaFuncSetAttribute(stageA_kernel,
                         cudaFuncAttributeMaxDynamicSharedMemorySize, SMEMA_BYTES);
    cudaFuncSetAttribute(stageB_mma,
                         cudaFuncAttributeMaxDynamicSharedMemorySize, SMEMB_BYTES);

    buildW_kernel<<<(TILES * Gg * 64 + 255) / 256, 256>>>(cWih, cWhh);
    stageA_kernel<<<dim3(64, 16), 256, SMEMA_BYTES>>>(x, typ, regs, Wih, Whh, bih, bhh);
    stageB_mma<<<Bn / 128, 256, SMEMB_BYTES>>>(regs, typ, c, cbih, cbhh, out);
}

// round 8
// speedup vs baseline: 2.8808x; 2.8808x over previous
#include <cuda_runtime.h>
#include <cuda_fp16.h>
#include <cstdint>

#define DEV __device__ __forceinline__

constexpr int Bn    = 65536;   // batch
constexpr int Hh    = 64;      // hidden
constexpr int Gg    = 192;     // 3*H
constexpr int Kf    = 1024;    // T*H
constexpr int Tt    = 16;      // type count
constexpr int TILES = 17;      // 16 register tiles + 1 c tile (64 k each)
constexpr int WTILE_BYTES = Gg * 128;   // 192 rows x 128B (64 fp16) = 24576

// ---- device-global scratch (no allocations allowed) ----
__device__ float g_hidden[(size_t)Bn * Hh];                       // stage A output
__device__ __align__(16) unsigned char g_Wq[TILES * WTILE_BYTES]; // fp16 W, tile-swizzled

// single dynamic shared memory declaration shared by all kernels
extern __shared__ __align__(1024) char dynsm[];

DEV float sigm(float v) { return 1.0f / (1.0f + __expf(-v)); }

DEV uint32_t smem_u32(const void* p) {
    uint32_t a;
    asm("{ .reg .u64 t; cvta.to.shared.u64 t, %1; cvt.u32.u64 %0, t; }" : "=r"(a) : "l"(p));
    return a;
}
DEV uint32_t sw128(uint32_t off) { return off ^ ((off >> 3) & 0x70); }

DEV void ldsm4(uint32_t* r, uint32_t addr) {
    asm volatile("ldmatrix.sync.aligned.m8n8.x4.shared.b16 {%0,%1,%2,%3}, [%4];"
        : "=r"(r[0]), "=r"(r[1]), "=r"(r[2]), "=r"(r[3]) : "r"(addr));
}
DEV void mma_f16(float* d, const uint32_t* a, const uint32_t* b) {
    asm volatile(
        "mma.sync.aligned.m16n8k16.row.col.f32.f16.f16.f32 "
        "{%0,%1,%2,%3}, {%4,%5,%6,%7}, {%8,%9}, {%0,%1,%2,%3};"
        : "+f"(d[0]), "+f"(d[1]), "+f"(d[2]), "+f"(d[3])
        : "r"(a[0]), "r"(a[1]), "r"(a[2]), "r"(a[3]), "r"(b[0]), "r"(b[1]));
}
DEV void cp16(uint32_t smem, const void* g) {
    asm volatile("cp.async.cg.shared.global [%0], [%1], 16;" :: "r"(smem), "l"(g));
}
DEV void cp_commit() { asm volatile("cp.async.commit_group;" ::: "memory"); }
DEV void cp_wait0()  { asm volatile("cp.async.wait_group 0;" ::: "memory"); }

DEV uint32_t packh2(float a, float b) {
    __half2 h = __floats2half2_rn(a, b);
    return *reinterpret_cast<uint32_t*>(&h);
}

// ---------------------------------------------------------------------------
// buildW: core weights -> fp16, stored per-64k-tile in the exact SW128 smem
// layout (GEMM's W load is then a raw cp.async copy).
// Wt[g][k] = cWih[g][k] (k<1024) else cWhh[g][k-1024]; tile t covers k=t*64..
// ---------------------------------------------------------------------------
__global__ void buildW_kernel(const float* __restrict__ cWih, const float* __restrict__ cWhh) {
    int idx = blockIdx.x * 256 + threadIdx.x;
    if (idx >= TILES * Gg * 64) return;
    int t   = idx / (Gg * 64);
    int rem = idx - t * (Gg * 64);
    int r   = rem >> 6;          // gate row 0..191
    int kk  = rem & 63;
    int k   = t * 64 + kk;
    float val = (k < Kf) ? cWih[(size_t)r * Kf + k] : cWhh[r * Hh + (k - Kf)];
    uint32_t off = sw128((uint32_t)(r * 128 + kk * 2));
    *(__half*)(g_Wq + (size_t)t * WTILE_BYTES + off) = __float2half_rn(val);
}

// ---------------------------------------------------------------------------
// Stage A: per-(type, chunk) block. Compact matching rows, run the per-type
// GRU (gi = Wih@x + bih, gh = Whh@reg + bhh) -> g_hidden.  (unchanged)
// ---------------------------------------------------------------------------
constexpr int SMEMA_BYTES = (64 * Gg * 2 + 2048 * 2 + 1024 + 8) * 4;

__global__ void __launch_bounds__(256, 1)
stageA_kernel(const float* __restrict__ x, const int* __restrict__ typ,
              const float* __restrict__ regs,
              const float* __restrict__ Wih, const float* __restrict__ Whh,
              const float* __restrict__ bih, const float* __restrict__ bhh)
{
    float* sm = (float*)dynsm;
    float* WI = sm;
    float* WH = WI + 64 * Gg;
    float* xs = WH + 64 * Gg;
    float* rs = xs + 2048;
    int*  list = (int*)(rs + 2048);
    int*  pcnt = list + 1024;

    const int tid = threadIdx.x;
    const int t   = blockIdx.y;
    const int c0  = blockIdx.x * 1024;

    if (tid == 0) *pcnt = 0;
    __syncthreads();
    for (int i = tid; i < 1024; i += 256) {
        if (typ[c0 + i] == t) list[atomicAdd(pcnt, 1)] = c0 + i;
    }
    __syncthreads();
    const int n = *pcnt;
    if (n == 0) return;

    if (tid < Gg) {
        const float* wi = Wih + ((size_t)t * Gg + tid) * 64;
        const float* wh = Whh + ((size_t)t * Gg + tid) * 64;
        #pragma unroll
        for (int q = 0; q < 16; q++) {
            float4 a = *(const float4*)(wi + q * 4);
            WI[(q*4+0)*Gg + tid] = a.x; WI[(q*4+1)*Gg + tid] = a.y;
            WI[(q*4+2)*Gg + tid] = a.z; WI[(q*4+3)*Gg + tid] = a.w;
            float4 b = *(const float4*)(wh + q * 4);
            WH[(q*4+0)*Gg + tid] = b.x; WH[(q*4+1)*Gg + tid] = b.y;
            WH[(q*4+2)*Gg + tid] = b.z; WH[(q*4+3)*Gg + tid] = b.w;
        }
    }
    __syncthreads();

    const int w = tid >> 5, l = tid & 31;
    const float* bip = bih + t * Gg + 2 * l;
    const float* bhp = bhh + t * Gg + 2 * l;
    const float2 bI0 = *(const float2*)(bip),      bI1 = *(const float2*)(bip + 64),
                 bI2 = *(const float2*)(bip + 128);
    const float2 bH0 = *(const float2*)(bhp),      bH1 = *(const float2*)(bhp + 64),
                 bH2 = *(const float2*)(bhp + 128);
    float* xw = xs + w * 256;
    float* rw = rs + w * 256;

    for (int base = w * 4; base < n; base += 32) {
        int bi4[4];
        #pragma unroll
        for (int i = 0; i < 4; i++) {
            int j = base + i; if (j > n - 1) j = n - 1;
            bi4[i] = list[j];
        }
        #pragma unroll
        for (int i = 0; i < 4; i++) {
            *(float2*)(xw + i * 64 + 2 * l) = *(const float2*)(x    + (size_t)bi4[i] * 64 + 2 * l);
            *(float2*)(rw + i * 64 + 2 * l) = *(const float2*)(regs + (size_t)bi4[i] * Kf + t * 64 + 2 * l);
        }
        __syncwarp();

        float2 gi0[4], gi1[4], gi2[4], gh0[4], gh1[4], gh2[4];
        #pragma unroll
        for (int i = 0; i < 4; i++) {
            gi0[i] = bI0; gi1[i] = bI1; gi2[i] = bI2;
            gh0[i] = bH0; gh1[i] = bH1; gh2[i] = bH2;
        }

        #pragma unroll 4
        for (int k = 0; k < 64; k++) {
            const float* wk = WI + k * Gg + 2 * l;
            float2 wi0 = *(const float2*)(wk),       wi1 = *(const float2*)(wk + 64),
                   wi2 = *(const float2*)(wk + 128);
            const float* hk = WH + k * Gg + 2 * l;
            float2 wh0 = *(const float2*)(hk),       wh1 = *(const float2*)(hk + 64),
                   wh2 = *(const float2*)(hk + 128);
            #pragma unroll
            for (int i = 0; i < 4; i++) {
                float xv = xw[i * 64 + k];
                float rv = rw[i * 64 + k];
                gi0[i].x = fmaf(wi0.x, xv, gi0[i].x); gi0[i].y = fmaf(wi0.y, xv, gi0[i].y);
                gi1[i].x = fmaf(wi1.x, xv, gi1[i].x); gi1[i].y = fmaf(wi1.y, xv, gi1[i].y);
                gi2[i].x = fmaf(wi2.x, xv, gi2[i].x); gi2[i].y = fmaf(wi2.y, xv, gi2[i].y);
                gh0[i].x = fmaf(wh0.x, rv, gh0[i].x); gh0[i].y = fmaf(wh0.y, rv, gh0[i].y);
                gh1[i].x = fmaf(wh1.x, rv, gh1[i].x); gh1[i].y = fmaf(wh1.y, rv, gh1[i].y);
                gh2[i].x = fmaf(wh2.x, rv, gh2[i].x); gh2[i].y = fmaf(wh2.y, rv, gh2[i].y);
            }
        }

        #pragma unroll
        for (int i = 0; i < 4; i++) {
            if (base + i < n) {
                float2 hv = *(const float2*)(rw + i * 64 + 2 * l);
                float r0 = sigm(gi0[i].x + gh0[i].x);
                float z0 = sigm(gi1[i].x + gh1[i].x);
                float n0 = tanhf(gi2[i].x + r0 * gh2[i].x);
                float o0 = (1.0f - z0) * n0 + z0 * hv.x;
                float r1 = sigm(gi0[i].y + gh0[i].y);
                float z1 = sigm(gi1[i].y + gh1[i].y);
                float n1 = tanhf(gi2[i].y + r1 * gh2[i].y);
                float o1 = (1.0f - z1) * n1 + z1 * hv.y;
                *(float2*)(g_hidden + (size_t)bi4[i] * 64 + 2 * l) = make_float2(o0, o1);
            }
        }
        __syncwarp();
    }
}

// ---------------------------------------------------------------------------
// Stage B: warp mma.sync fp16 2-pass GEMM (A split hi/lo, W single fp16).
// M-tile 64, N=192, K=17x64; 2 CTAs/SM. c-tile first -> snapshot hn ->
// keep accumulating; epilogue n_pre = acc_n + (r-1)*hn.
// smem (dyn, per CTA): [0,8K) Ahi | [8K,16K) Alo | [16K,40K) W fp16
//   epilogue overlay: Ds[64][200] @0 (51200) | cs[64][68] @51200 (17408)
//   Hn[64][64] @68608 (16384) -> total 84992
// ---------------------------------------------------------------------------
constexpr int SB_ALO = 8192;
constexpr int SB_W   = 16384;
constexpr int SB_DS  = 0;
constexpr int SB_CS  = 51200;
constexpr int SB_HN  = 68608;
constexpr int SMEMB_BYTES = 84992;

__global__ void __launch_bounds__(256, 2)
stageB_mma(const float* __restrict__ regs, const int* __restrict__ typ,
           const float* __restrict__ c,
           const float* __restrict__ cbih, const float* __restrict__ cbhh,
           float* __restrict__ out)
{
    char* sm = dynsm;
    const uint32_t sb = smem_u32(sm);
    __shared__ int styp[64];

    const int tid  = threadIdx.x;
    const int wid  = tid >> 5, lane = tid & 31;
    const int wm   = wid & 1;      // m block: rows wm*32
    const int wn   = wid >> 1;     // n block: cols wn*48
    const int bm   = blockIdx.x * 64;

    if (tid < 64) styp[tid] = typ[bm + tid];
    __syncthreads();

    float acc[2][6][4];
    #pragma unroll
    for (int a = 0; a < 2; a++)
        #pragma unroll
        for (int b = 0; b < 6; b++)
            #pragma unroll
            for (int r = 0; r < 4; r++) acc[a][b][r] = 0.0f;

    const int arow = tid >> 2;      // A loader: row 0..63
    const int aqd  = tid & 3;       // 16-float quarter

    float4 pf[4];                   // A prefetch registers (16 floats)
    auto prefetchA = [&](int t) {
        const float* srow;
        if (t < Tt) {
            srow = (styp[arow] == t)
                     ? (g_hidden + (size_t)(bm + arow) * 64)
                     : (regs + (size_t)(bm + arow) * Kf + t * 64);
        } else {
            srow = c + (size_t)(bm + arow) * 64;
        }
        #pragma unroll
        for (int i = 0; i < 4; i++)
            pf[i] = *(const float4*)(srow + aqd * 16 + i * 4);
    };
    auto storeA = [&]() {
        float f[16];
        #pragma unroll
        for (int i = 0; i < 4; i++) {
            f[4*i] = pf[i].x; f[4*i+1] = pf[i].y; f[4*i+2] = pf[i].z; f[4*i+3] = pf[i].w;
        }
        uint32_t hp[8], lp[8];
        #pragma unroll
        for (int i = 0; i < 8; i++) {
            float a0 = f[2*i], a1 = f[2*i+1];
            __half h0 = __float2half_rn(a0), h1 = __float2half_rn(a1);
            hp[i] = ((uint32_t)__half_as_ushort(h1) << 16) | __half_as_ushort(h0);
            lp[i] = packh2(a0 - __half2float(h0), a1 - __half2float(h1));
        }
        uint32_t base = (uint32_t)(arow * 128 + aqd * 32);
        uint32_t o0 = sw128(base), o1 = sw128(base + 16);
        *(uint4*)(sm + o0)          = make_uint4(hp[0], hp[1], hp[2], hp[3]);
        *(uint4*)(sm + o1)          = make_uint4(hp[4], hp[5], hp[6], hp[7]);
        *(uint4*)(sm + SB_ALO + o0) = make_uint4(lp[0], lp[1], lp[2], lp[3]);
        *(uint4*)(sm + SB_ALO + o1) = make_uint4(lp[4], lp[5], lp[6], lp[7]);
    };
    auto loadW = [&](int t) {
        const unsigned char* src = g_Wq + (size_t)t * WTILE_BYTES;
        #pragma unroll
        for (int j = 0; j < 6; j++) {
            int i = (tid + j * 256) * 16;
            cp16(sb + SB_W + i, src + i);
        }
    };

    const int l8 = lane & 7, li = lane >> 3;
    const int am_off = (li & 1) * 8, ak_off = (li >> 1) * 8;
    const int wn_off = (li >> 1) * 8, wk_off = (li & 1) * 8;

    // prologue: prefetch c-tile (t=16)
    prefetchA(16);

    for (int it = 0; it <= 16; it++) {
        const int t = (it == 0) ? 16 : it - 1;
        __syncthreads();                       // prev compute done with A & W
        loadW(t);
        cp_commit();
        storeA();
        if (it < 16) prefetchA(it);            // LDG for next tile, overlaps compute
        cp_wait0();
        __syncthreads();

        // compute: 2-pass (Ahi*W + Alo*W)
        #pragma unroll
        for (int ks = 0; ks < 4; ks++) {
            const int k0 = ks * 16;
            uint32_t ah[2][4], al[2][4];
            #pragma unroll
            for (int mt = 0; mt < 2; mt++) {
                int row = wm * 32 + mt * 16 + am_off + l8;
                uint32_t off = sw128((uint32_t)(row * 128 + (k0 + ak_off) * 2));
                ldsm4(ah[mt], sb + off);
                ldsm4(al[mt], sb + SB_ALO + off);
            }
            #pragma unroll
            for (int np = 0; np < 3; np++) {
                int nrow = wn * 48 + np * 16 + wn_off + l8;
                uint32_t wf[4];
                ldsm4(wf, sb + SB_W + sw128((uint32_t)(nrow * 128 + (k0 + wk_off) * 2)));
                #pragma unroll
                for (int mt = 0; mt < 2; mt++) {
                    mma_f16(acc[mt][2*np],   ah[mt], wf);
                    mma_f16(acc[mt][2*np],   al[mt], wf);
                    mma_f16(acc[mt][2*np+1], ah[mt], wf + 2);
                    mma_f16(acc[mt][2*np+1], al[mt], wf + 2);
                }
            }
        }

        if (it == 0) {
            // snapshot hn = c @ cWhh_n^T (global cols 128..191)
            float* Hn = (float*)(sm + SB_HN);
            #pragma unroll
            for (int mt = 0; mt < 2; mt++)
                #pragma unroll
                for (int nt = 0; nt < 6; nt++) {
                    int colb = wn * 48 + nt * 8;
                    if (colb >= 128) {
                        #pragma unroll
                        for (int r = 0; r < 4; r++) {
                            int row = wm * 32 + mt * 16 + (lane >> 2) + ((r >> 1) << 3);
                            int col = colb - 128 + ((lane & 3) << 1) + (r & 1);
                            Hn[row * 64 + col] = acc[mt][nt][r];
                        }
                    }
                }
        }
    }
    __syncthreads();

    // ---- epilogue ----
    float* Ds = (float*)(sm + SB_DS);    // [64][200]
    float* cs = (float*)(sm + SB_CS);    // [64][68]
    float* Hn = (float*)(sm + SB_HN);    // [64][64]

    #pragma unroll
    for (int mt = 0; mt < 2; mt++)
        #pragma unroll
        for (int nt = 0; nt < 6; nt++)
            #pragma unroll
            for (int r = 0; r < 4; r++) {
                int row = wm * 32 + mt * 16 + (lane >> 2) + ((r >> 1) << 3);
                int col = wn * 48 + nt * 8 + ((lane & 3) << 1) + (r & 1);
                Ds[row * 200 + col] = acc[mt][nt][r];
            }
    #pragma unroll
    for (int j = 0; j < 4; j++) {
        int i   = tid + j * 256;      // 1024 float4 slots
        int row = i >> 4, q = i & 15;
        float4 v = *(const float4*)(c + (size_t)(bm + row) * 64 + q * 4);
        *(float4*)(cs + row * 68 + q * 4) = v;
    }
    __syncthreads();

    const int h  = tid & 63;
    const int rl = tid >> 6;
    const float bR  = cbih[h]       + cbhh[h];
    const float bZ  = cbih[64 + h]  + cbhh[64 + h];
    const float bN  = cbih[128 + h];
    const float bHN = cbhh[128 + h];
    #pragma unroll 4
    for (int i = 0; i < 16; i++) {
        int row = rl + i * 4;
        float ar = Ds[row * 200 + h];
        float az = Ds[row * 200 + 64 + h];
        float an = Ds[row * 200 + 128 + h];
        float hn = Hn[row * 64 + h];
        float cv = cs[row * 68 + h];
        float rv = sigm(ar + bR);
        float zv = sigm(az + bZ);
        float nv = tanhf(an + bN + rv * bHN + (rv - 1.0f) * hn);
        out[(size_t)(bm + row) * 64 + h] = (1.0f - zv) * nv + zv * cv;
    }
}

// ---------------------------------------------------------------------------
extern "C" void kernel_launch(void* const* d_in, const int* in_sizes, int n_in,
                              void* d_out, int out_size)
{
    const float* x    = (const float*)d_in[0];
    const int*   typ  = (const int*)  d_in[1];
    const float* c    = (const float*)d_in[2];
    const float* regs = (const float*)d_in[3];
    const float* Wih  = (const float*)d_in[4];
    const float* Whh  = (const float*)d_in[5];
    const float* bih  = (const float*)d_in[6];
    const float* bhh  = (const float*)d_in[7];
    const float* cWih = (const float*)d_in[8];
    const float* cWhh = (const float*)d_in[9];
    const float* cbih = (const float*)d_in[10];
    const float* cbhh = (const float*)d_in[11];
    float* out = (float*)d_out;

    (void)in_sizes; (void)n_in; (void)out_size;

    cudaFuncSetAttribute(stageA_kernel,
                         cudaFuncAttributeMaxDynamicSharedMemorySize, SMEMA_BYTES);
    cudaFuncSetAttribute(stageB_mma,
                         cudaFuncAttributeMaxDynamicSharedMemorySize, SMEMB_BYTES);

    // order: stageA first (independent of buildW) so ncu's fixed capture slot
    // lands on stageA and pins down the A/B time split.
    stageA_kernel<<<dim3(64, 16), 256, SMEMA_BYTES>>>(x, typ, regs, Wih, Whh, bih, bhh);
    buildW_kernel<<<(TILES * Gg * 64 + 255) / 256, 256>>>(cWih, cWhh);
    stageB_mma<<<Bn / 64, 256, SMEMB_BYTES>>>(regs, typ, c, cbih, cbhh, out);
}

// round 9
// speedup vs baseline: 4.0571x; 1.4083x over previous
#include <cuda_runtime.h>
#include <cuda_fp16.h>
#include <cstdint>

#define DEV __device__ __forceinline__

constexpr int Bn    = 65536;   // batch
constexpr int Hh    = 64;      // hidden
constexpr int Gg    = 192;     // 3*H
constexpr int Kf    = 1024;    // T*H
constexpr int Tt    = 16;      // type count
constexpr int TILES = 17;      // 16 register tiles + 1 c tile (64 k each)
constexpr int WTILE_BYTES = Gg * 128;   // 192 rows x 128B (64 fp16) = 24576

// ---- device-global scratch (no allocations allowed) ----
__device__ float g_hidden[(size_t)Bn * Hh];                       // stage A output
__device__ __align__(16) unsigned char g_Wq[TILES * WTILE_BYTES]; // stage B W fp16, tile-swizzled
__device__ __align__(16) unsigned char g_WA[Tt * 2 * WTILE_BYTES];// stage A W bank: (t,phase) phase0=Whh,1=Wih

// single dynamic shared memory declaration shared by all kernels
extern __shared__ __align__(1024) char dynsm[];

DEV float sigm(float v) { return 1.0f / (1.0f + __expf(-v)); }

DEV uint32_t smem_u32(const void* p) {
    uint32_t a;
    asm("{ .reg .u64 t; cvta.to.shared.u64 t, %1; cvt.u32.u64 %0, t; }" : "=r"(a) : "l"(p));
    return a;
}
DEV uint32_t sw128(uint32_t off) { return off ^ ((off >> 3) & 0x70); }

DEV void ldsm4(uint32_t* r, uint32_t addr) {
    asm volatile("ldmatrix.sync.aligned.m8n8.x4.shared.b16 {%0,%1,%2,%3}, [%4];"
        : "=r"(r[0]), "=r"(r[1]), "=r"(r[2]), "=r"(r[3]) : "r"(addr));
}
DEV void mma_f16(float* d, const uint32_t* a, const uint32_t* b) {
    asm volatile(
        "mma.sync.aligned.m16n8k16.row.col.f32.f16.f16.f32 "
        "{%0,%1,%2,%3}, {%4,%5,%6,%7}, {%8,%9}, {%0,%1,%2,%3};"
        : "+f"(d[0]), "+f"(d[1]), "+f"(d[2]), "+f"(d[3])
        : "r"(a[0]), "r"(a[1]), "r"(a[2]), "r"(a[3]), "r"(b[0]), "r"(b[1]));
}
DEV void cp16(uint32_t smem, const void* g) {
    asm volatile("cp.async.cg.shared.global [%0], [%1], 16;" :: "r"(smem), "l"(g));
}
DEV void cp_commit() { asm volatile("cp.async.commit_group;" ::: "memory"); }
DEV void cp_wait0()  { asm volatile("cp.async.wait_group 0;" ::: "memory"); }

DEV uint32_t packh2(float a, float b) {
    __half2 h = __floats2half2_rn(a, b);
    return *reinterpret_cast<uint32_t*>(&h);
}

// ---------------------------------------------------------------------------
// buildA: per-type stage-A weight bank -> fp16 SW128 tiles.
// g_WA[(t*2+p)] tile: rows 0..191 = gate rows, cols = k 0..63.
// p=0: Whh[t], p=1: Wih[t].
// ---------------------------------------------------------------------------
__global__ void buildA_kernel(const float* __restrict__ Wih, const float* __restrict__ Whh) {
    int idx = blockIdx.x * 256 + threadIdx.x;
    if (idx >= Tt * 2 * Gg * 64) return;
    int t   = idx / (2 * Gg * 64);
    int rem = idx - t * (2 * Gg * 64);
    int p   = rem / (Gg * 64);
    int r2  = rem - p * (Gg * 64);
    int r   = r2 >> 6;
    int kk  = r2 & 63;
    const float* src = (p == 0) ? Whh : Wih;
    float val = src[((size_t)t * Gg + r) * 64 + kk];
    uint32_t off = sw128((uint32_t)(r * 128 + kk * 2));
    *(__half*)(g_WA + (size_t)(t * 2 + p) * WTILE_BYTES + off) = __float2half_rn(val);
}

// ---------------------------------------------------------------------------
// buildB: stage-B core weights -> fp16 SW128 tiles (as in R8).
// ---------------------------------------------------------------------------
__global__ void buildB_kernel(const float* __restrict__ cWih, const float* __restrict__ cWhh) {
    int idx = blockIdx.x * 256 + threadIdx.x;
    if (idx >= TILES * Gg * 64) return;
    int t   = idx / (Gg * 64);
    int rem = idx - t * (Gg * 64);
    int r   = rem >> 6;
    int kk  = rem & 63;
    int k   = t * 64 + kk;
    float val = (k < Kf) ? cWih[(size_t)r * Kf + k] : cWhh[r * Hh + (k - Kf)];
    uint32_t off = sw128((uint32_t)(r * 128 + kk * 2));
    *(__half*)(g_Wq + (size_t)t * WTILE_BYTES + off) = __float2half_rn(val);
}

// ---------------------------------------------------------------------------
// Stage A (mma): per-(type, chunk) block. Compact matching rows, then GEMM
// A=[reg | x] (K=128) vs W=[Whh | Wih] with fp16 2-pass A-split.
// Phase 0 (Whh@reg) first -> snapshot hn cols -> accumulate phase 1 (Wih@x).
// Epilogue: GRU with n_pre = acc_n + (r-1)*hn -> g_hidden.
// smem: AHI 0..8K | ALO 8K..16K | W 16K..40K ; overlay Ds[64][200] 0..51200
//       REG f32 @51200 (16K) | HN @67584 (16K) -> 83968 total
// ---------------------------------------------------------------------------
constexpr int A_ALO = 8192;
constexpr int A_W   = 16384;
constexpr int A_REG = 51200;
constexpr int A_HN  = 67584;
constexpr int SMEMA_BYTES = 83968;

__global__ void __launch_bounds__(256, 2)
stageA_mma(const float* __restrict__ x, const int* __restrict__ typ,
           const float* __restrict__ regs,
           const float* __restrict__ bih, const float* __restrict__ bhh)
{
    char* sm = dynsm;
    const uint32_t sb = smem_u32(sm);
    __shared__ int list[1024];
    __shared__ int pcnt;

    const int tid = threadIdx.x;
    const int wid = tid >> 5, lane = tid & 31;
    const int t   = blockIdx.y;
    const int c0  = blockIdx.x * 1024;

    if (tid == 0) pcnt = 0;
    __syncthreads();
    for (int i = tid; i < 1024; i += 256) {
        if (typ[c0 + i] == t) list[atomicAdd(&pcnt, 1)] = c0 + i;
    }
    __syncthreads();
    const int n = pcnt;
    if (n == 0) return;

    // hoisted per-type biases (h = tid&63 lane in epilogue)
    const int h  = tid & 63;
    const int rl = tid >> 6;
    const float bR  = bih[t * Gg + h]        + bhh[t * Gg + h];
    const float bZ  = bih[t * Gg + 64 + h]   + bhh[t * Gg + 64 + h];
    const float bN  = bih[t * Gg + 128 + h];
    const float bHN = bhh[t * Gg + 128 + h];

    const int arow = tid >> 2;      // gather: row 0..63
    const int aqd  = tid & 3;       // 16-float quarter

    const int l8 = lane & 7, li = lane >> 3;
    const int am_off = (li & 1) * 8, ak_off = (li >> 1) * 8;
    const int wn_off = (li >> 1) * 8, wk_off = (li & 1) * 8;
    const int wm = wid & 1;         // rows wm*32
    const int wn = wid >> 1;        // cols wn*48

    float* REG = (float*)(sm + A_REG);
    float* Hn  = (float*)(sm + A_HN);
    float* Ds  = (float*)sm;

    for (int base = 0; base < n; base += 64) {
        const int m = (n - base < 64) ? (n - base) : 64;

        float acc[2][6][4];
        #pragma unroll
        for (int a = 0; a < 2; a++)
            #pragma unroll
            for (int b = 0; b < 6; b++)
                #pragma unroll
                for (int r = 0; r < 4; r++) acc[a][b][r] = 0.0f;

        int gj = base + arow; if (gj > n - 1) gj = n - 1;
        const int gb = list[gj];

        // ================= phase 0: Whh @ reg =================
        {   // W load (cp.async) + gather reg rows (keep fp32 copy for epilogue)
            const unsigned char* wsrc = g_WA + (size_t)(t * 2 + 0) * WTILE_BYTES;
            #pragma unroll
            for (int j = 0; j < 6; j++) {
                int i = (tid + j * 256) * 16;
                cp16(sb + A_W + i, wsrc + i);
            }
            cp_commit();
            const float* srow = regs + (size_t)gb * Kf + t * 64;
            float f[16];
            #pragma unroll
            for (int i = 0; i < 4; i++) {
                float4 v = *(const float4*)(srow + aqd * 16 + i * 4);
                f[4*i] = v.x; f[4*i+1] = v.y; f[4*i+2] = v.z; f[4*i+3] = v.w;
                *(float4*)(REG + arow * 64 + aqd * 16 + i * 4) = v;
            }
            uint32_t hp[8], lp[8];
            #pragma unroll
            for (int i = 0; i < 8; i++) {
                float a0 = f[2*i], a1 = f[2*i+1];
                __half h0 = __float2half_rn(a0), h1 = __float2half_rn(a1);
                hp[i] = ((uint32_t)__half_as_ushort(h1) << 16) | __half_as_ushort(h0);
                lp[i] = packh2(a0 - __half2float(h0), a1 - __half2float(h1));
            }
            uint32_t bo = (uint32_t)(arow * 128 + aqd * 32);
            uint32_t o0 = sw128(bo), o1 = sw128(bo + 16);
            *(uint4*)(sm + o0)         = make_uint4(hp[0], hp[1], hp[2], hp[3]);
            *(uint4*)(sm + o1)         = make_uint4(hp[4], hp[5], hp[6], hp[7]);
            *(uint4*)(sm + A_ALO + o0) = make_uint4(lp[0], lp[1], lp[2], lp[3]);
            *(uint4*)(sm + A_ALO + o1) = make_uint4(lp[4], lp[5], lp[6], lp[7]);
        }
        cp_wait0();
        __syncthreads();

        #pragma unroll
        for (int ks = 0; ks < 4; ks++) {
            const int k0 = ks * 16;
            uint32_t ah[2][4], al[2][4];
            #pragma unroll
            for (int mt = 0; mt < 2; mt++) {
                int row = wm * 32 + mt * 16 + am_off + l8;
                uint32_t off = sw128((uint32_t)(row * 128 + (k0 + ak_off) * 2));
                ldsm4(ah[mt], sb + off);
                ldsm4(al[mt], sb + A_ALO + off);
            }
            #pragma unroll
            for (int np = 0; np < 3; np++) {
                int nrow = wn * 48 + np * 16 + wn_off + l8;
                uint32_t wf[4];
                ldsm4(wf, sb + A_W + sw128((uint32_t)(nrow * 128 + (k0 + wk_off) * 2)));
                #pragma unroll
                for (int mt = 0; mt < 2; mt++) {
                    mma_f16(acc[mt][2*np],   ah[mt], wf);
                    mma_f16(acc[mt][2*np],   al[mt], wf);
                    mma_f16(acc[mt][2*np+1], ah[mt], wf + 2);
                    mma_f16(acc[mt][2*np+1], al[mt], wf + 2);
                }
            }
        }

        // snapshot hn = reg @ Whh_n^T (cols 128..191)
        #pragma unroll
        for (int mt = 0; mt < 2; mt++)
            #pragma unroll
            for (int nt = 0; nt < 6; nt++) {
                int colb = wn * 48 + nt * 8;
                if (colb >= 128) {
                    #pragma unroll
                    for (int r = 0; r < 4; r++) {
                        int row = wm * 32 + mt * 16 + (lane >> 2) + ((r >> 1) << 3);
                        int col = colb - 128 + ((lane & 3) << 1) + (r & 1);
                        Hn[row * 64 + col] = acc[mt][nt][r];
                    }
                }
            }
        __syncthreads();   // everyone done with phase-0 A/W before overwrite

        // ================= phase 1: Wih @ x (accumulate) =================
        {
            const unsigned char* wsrc = g_WA + (size_t)(t * 2 + 1) * WTILE_BYTES;
            #pragma unroll
            for (int j = 0; j < 6; j++) {
                int i = (tid + j * 256) * 16;
                cp16(sb + A_W + i, wsrc + i);
            }
            cp_commit();
            const float* srow = x + (size_t)gb * 64;
            float f[16];
            #pragma unroll
            for (int i = 0; i < 4; i++) {
                float4 v = *(const float4*)(srow + aqd * 16 + i * 4);
                f[4*i] = v.x; f[4*i+1] = v.y; f[4*i+2] = v.z; f[4*i+3] = v.w;
            }
            uint32_t hp[8], lp[8];
            #pragma unroll
            for (int i = 0; i < 8; i++) {
                float a0 = f[2*i], a1 = f[2*i+1];
                __half h0 = __float2half_rn(a0), h1 = __float2half_rn(a1);
                hp[i] = ((uint32_t)__half_as_ushort(h1) << 16) | __half_as_ushort(h0);
                lp[i] = packh2(a0 - __half2float(h0), a1 - __half2float(h1));
            }
            uint32_t bo = (uint32_t)(arow * 128 + aqd * 32);
            uint32_t o0 = sw128(bo), o1 = sw128(bo + 16);
            *(uint4*)(sm + o0)         = make_uint4(hp[0], hp[1], hp[2], hp[3]);
            *(uint4*)(sm + o1)         = make_uint4(hp[4], hp[5], hp[6], hp[7]);
            *(uint4*)(sm + A_ALO + o0) = make_uint4(lp[0], lp[1], lp[2], lp[3]);
            *(uint4*)(sm + A_ALO + o1) = make_uint4(lp[4], lp[5], lp[6], lp[7]);
        }
        cp_wait0();
        __syncthreads();

        #pragma unroll
        for (int ks = 0; ks < 4; ks++) {
            const int k0 = ks * 16;
            uint32_t ah[2][4], al[2][4];
            #pragma unroll
            for (int mt = 0; mt < 2; mt++) {
                int row = wm * 32 + mt * 16 + am_off + l8;
                uint32_t off = sw128((uint32_t)(row * 128 + (k0 + ak_off) * 2));
                ldsm4(ah[mt], sb + off);
                ldsm4(al[mt], sb + A_ALO + off);
            }
            #pragma unroll
            for (int np = 0; np < 3; np++) {
                int nrow = wn * 48 + np * 16 + wn_off + l8;
                uint32_t wf[4];
                ldsm4(wf, sb + A_W + sw128((uint32_t)(nrow * 128 + (k0 + wk_off) * 2)));
                #pragma unroll
                for (int mt = 0; mt < 2; mt++) {
                    mma_f16(acc[mt][2*np],   ah[mt], wf);
                    mma_f16(acc[mt][2*np],   al[mt], wf);
                    mma_f16(acc[mt][2*np+1], ah[mt], wf + 2);
                    mma_f16(acc[mt][2*np+1], al[mt], wf + 2);
                }
            }
        }
        __syncthreads();   // all warps done with A/W before Ds overlay

        // ---- epilogue: Ds overlay + fused GRU -> g_hidden ----
        #pragma unroll
        for (int mt = 0; mt < 2; mt++)
            #pragma unroll
            for (int nt = 0; nt < 6; nt++)
                #pragma unroll
                for (int r = 0; r < 4; r++) {
                    int row = wm * 32 + mt * 16 + (lane >> 2) + ((r >> 1) << 3);
                    int col = wn * 48 + nt * 8 + ((lane & 3) << 1) + (r & 1);
                    Ds[row * 200 + col] = acc[mt][nt][r];
                }
        __syncthreads();

        #pragma unroll 4
        for (int i = 0; i < 16; i++) {
            int row = rl + i * 4;
            if (row < m) {
                float ar = Ds[row * 200 + h];
                float az = Ds[row * 200 + 64 + h];
                float an = Ds[row * 200 + 128 + h];
                float hn = Hn[row * 64 + h];
                float rg = REG[row * 64 + h];
                float rv = sigm(ar + bR);
                float zv = sigm(az + bZ);
                float nv = tanhf(an + bN + rv * bHN + (rv - 1.0f) * hn);
                g_hidden[(size_t)list[base + row] * 64 + h] = (1.0f - zv) * nv + zv * rg;
            }
        }
        __syncthreads();   // Ds/REG/HN free before next group's gather
    }
}

// ---------------------------------------------------------------------------
// Stage B: warp mma.sync fp16 2-pass GEMM (unchanged from R8 @ 308 us).
// ---------------------------------------------------------------------------
constexpr int SB_ALO = 8192;
constexpr int SB_W   = 16384;
constexpr int SB_DS  = 0;
constexpr int SB_CS  = 51200;
constexpr int SB_HN  = 68608;
constexpr int SMEMB_BYTES = 84992;

__global__ void __launch_bounds__(256, 2)
stageB_mma(const float* __restrict__ regs, const int* __restrict__ typ,
           const float* __restrict__ c,
           const float* __restrict__ cbih, const float* __restrict__ cbhh,
           float* __restrict__ out)
{
    char* sm = dynsm;
    const uint32_t sb = smem_u32(sm);
    __shared__ int styp[64];

    const int tid  = threadIdx.x;
    const int wid  = tid >> 5, lane = tid & 31;
    const int wm   = wid & 1;
    const int wn   = wid >> 1;
    const int bm   = blockIdx.x * 64;

    if (tid < 64) styp[tid] = typ[bm + tid];
    __syncthreads();

    float acc[2][6][4];
    #pragma unroll
    for (int a = 0; a < 2; a++)
        #pragma unroll
        for (int b = 0; b < 6; b++)
            #pragma unroll
            for (int r = 0; r < 4; r++) acc[a][b][r] = 0.0f;

    const int arow = tid >> 2;
    const int aqd  = tid & 3;

    float4 pf[4];
    auto prefetchA = [&](int t) {
        const float* srow;
        if (t < Tt) {
            srow = (styp[arow] == t)
                     ? (g_hidden + (size_t)(bm + arow) * 64)
                     : (regs + (size_t)(bm + arow) * Kf + t * 64);
        } else {
            srow = c + (size_t)(bm + arow) * 64;
        }
        #pragma unroll
        for (int i = 0; i < 4; i++)
            pf[i] = *(const float4*)(srow + aqd * 16 + i * 4);
    };
    auto storeA = [&]() {
        float f[16];
        #pragma unroll
        for (int i = 0; i < 4; i++) {
            f[4*i] = pf[i].x; f[4*i+1] = pf[i].y; f[4*i+2] = pf[i].z; f[4*i+3] = pf[i].w;
        }
        uint32_t hp[8], lp[8];
        #pragma unroll
        for (int i = 0; i < 8; i++) {
            float a0 = f[2*i], a1 = f[2*i+1];
            __half h0 = __float2half_rn(a0), h1 = __float2half_rn(a1);
            hp[i] = ((uint32_t)__half_as_ushort(h1) << 16) | __half_as_ushort(h0);
            lp[i] = packh2(a0 - __half2float(h0), a1 - __half2float(h1));
        }
        uint32_t base = (uint32_t)(arow * 128 + aqd * 32);
        uint32_t o0 = sw128(base), o1 = sw128(base + 16);
        *(uint4*)(sm + o0)          = make_uint4(hp[0], hp[1], hp[2], hp[3]);
        *(uint4*)(sm + o1)          = make_uint4(hp[4], hp[5], hp[6], hp[7]);
        *(uint4*)(sm + SB_ALO + o0) = make_uint4(lp[0], lp[1], lp[2], lp[3]);
        *(uint4*)(sm + SB_ALO + o1) = make_uint4(lp[4], lp[5], lp[6], lp[7]);
    };
    auto loadW = [&](int t) {
        const unsigned char* src = g_Wq + (size_t)t * WTILE_BYTES;
        #pragma unroll
        for (int j = 0; j < 6; j++) {
            int i = (tid + j * 256) * 16;
            cp16(sb + SB_W + i, src + i);
        }
    };

    const int l8 = lane & 7, li = lane >> 3;
    const int am_off = (li & 1) * 8, ak_off = (li >> 1) * 8;
    const int wn_off = (li >> 1) * 8, wk_off = (li & 1) * 8;

    prefetchA(16);

    for (int it = 0; it <= 16; it++) {
        const int t = (it == 0) ? 16 : it - 1;
        __syncthreads();
        loadW(t);
        cp_commit();
        storeA();
        if (it < 16) prefetchA(it);
        cp_wait0();
        __syncthreads();

        #pragma unroll
        for (int ks = 0; ks < 4; ks++) {
            const int k0 = ks * 16;
            uint32_t ah[2][4], al[2][4];
            #pragma unroll
            for (int mt = 0; mt < 2; mt++) {
                int row = wm * 32 + mt * 16 + am_off + l8;
                uint32_t off = sw128((uint32_t)(row * 128 + (k0 + ak_off) * 2));
                ldsm4(ah[mt], sb + off);
                ldsm4(al[mt], sb + SB_ALO + off);
            }
            #pragma unroll
            for (int np = 0; np < 3; np++) {
                int nrow = wn * 48 + np * 16 + wn_off + l8;
                uint32_t wf[4];
                ldsm4(wf, sb + SB_W + sw128((uint32_t)(nrow * 128 + (k0 + wk_off) * 2)));
                #pragma unroll
                for (int mt = 0; mt < 2; mt++) {
                    mma_f16(acc[mt][2*np],   ah[mt], wf);
                    mma_f16(acc[mt][2*np],   al[mt], wf);
                    mma_f16(acc[mt][2*np+1], ah[mt], wf + 2);
                    mma_f16(acc[mt][2*np+1], al[mt], wf + 2);
                }
            }
        }

        if (it == 0) {
            float* Hn = (float*)(sm + SB_HN);
            #pragma unroll
            for (int mt = 0; mt < 2; mt++)
                #pragma unroll
                for (int nt = 0; nt < 6; nt++) {
                    int colb = wn * 48 + nt * 8;
                    if (colb >= 128) {
                        #pragma unroll
                        for (int r = 0; r < 4; r++) {
                            int row = wm * 32 + mt * 16 + (lane >> 2) + ((r >> 1) << 3);
                            int col = colb - 128 + ((lane & 3) << 1) + (r & 1);
                            Hn[row * 64 + col] = acc[mt][nt][r];
                        }
                    }
                }
        }
    }
    __syncthreads();

    float* Ds = (float*)(sm + SB_DS);
    float* cs = (float*)(sm + SB_CS);
    float* Hn = (float*)(sm + SB_HN);

    #pragma unroll
    for (int mt = 0; mt < 2; mt++)
        #pragma unroll
        for (int nt = 0; nt < 6; nt++)
            #pragma unroll
            for (int r = 0; r < 4; r++) {
                int row = wm * 32 + mt * 16 + (lane >> 2) + ((r >> 1) << 3);
                int col = wn * 48 + nt * 8 + ((lane & 3) << 1) + (r & 1);
                Ds[row * 200 + col] = acc[mt][nt][r];
            }
    #pragma unroll
    for (int j = 0; j < 4; j++) {
        int i   = tid + j * 256;
        int row = i >> 4, q = i & 15;
        float4 v = *(const float4*)(c + (size_t)(bm + row) * 64 + q * 4);
        *(float4*)(cs + row * 68 + q * 4) = v;
    }
    __syncthreads();

    const int h  = tid & 63;
    const int rl = tid >> 6;
    const float bR  = cbih[h]       + cbhh[h];
    const float bZ  = cbih[64 + h]  + cbhh[64 + h];
    const float bN  = cbih[128 + h];
    const float bHN = cbhh[128 + h];
    #pragma unroll 4
    for (int i = 0; i < 16; i++) {
        int row = rl + i * 4;
        float ar = Ds[row * 200 + h];
        float az = Ds[row * 200 + 64 + h];
        float an = Ds[row * 200 + 128 + h];
        float hn = Hn[row * 64 + h];
        float cv = cs[row * 68 + h];
        float rv = sigm(ar + bR);
        float zv = sigm(az + bZ);
        float nv = tanhf(an + bN + rv * bHN + (rv - 1.0f) * hn);
        out[(size_t)(bm + row) * 64 + h] = (1.0f - zv) * nv + zv * cv;
    }
}

// ---------------------------------------------------------------------------
extern "C" void kernel_launch(void* const* d_in, const int* in_sizes, int n_in,
                              void* d_out, int out_size)
{
    const float* x    = (const float*)d_in[0];
    const int*   typ  = (const int*)  d_in[1];
    const float* c    = (const float*)d_in[2];
    const float* regs = (const float*)d_in[3];
    const float* Wih  = (const float*)d_in[4];
    const float* Whh  = (const float*)d_in[5];
    const float* bih  = (const float*)d_in[6];
    const float* bhh  = (const float*)d_in[7];
    const float* cWih = (const float*)d_in[8];
    const float* cWhh = (const float*)d_in[9];
    const float* cbih = (const float*)d_in[10];
    const float* cbhh = (const float*)d_in[11];
    float* out = (float*)d_out;

    (void)in_sizes; (void)n_in; (void)out_size;

    cudaFuncSetAttribute(stageA_mma,
                         cudaFuncAttributeMaxDynamicSharedMemorySize, SMEMA_BYTES);
    cudaFuncSetAttribute(stageB_mma,
                         cudaFuncAttributeMaxDynamicSharedMemorySize, SMEMB_BYTES);

    buildA_kernel<<<(Tt * 2 * Gg * 64 + 255) / 256, 256>>>(Wih, Whh);
    stageA_mma<<<dim3(64, 16), 256, SMEMA_BYTES>>>(x, typ, regs, bih, bhh);
    buildB_kernel<<<(TILES * Gg * 64 + 255) / 256, 256>>>(cWih, cWhh);
    stageB_mma<<<Bn / 64, 256, SMEMB_BYTES>>>(regs, typ, c, cbih, cbhh, out);
}

// round 11
// speedup vs baseline: 4.9005x; 1.2079x over previous
#include <cuda_runtime.h>
#include <cuda_fp16.h>
#include <cstdint>

#define DEV __device__ __forceinline__

constexpr int Bn    = 65536;   // batch
constexpr int Hh    = 64;      // hidden
constexpr int Gg    = 192;     // 3*H
constexpr int Kf    = 1024;    // T*H
constexpr int Tt    = 16;      // type count
constexpr int TILES = 17;      // 16 register tiles + 1 c tile (64 k each)
constexpr int WTILE_BYTES = Gg * 128;   // 192 rows x 128B (64 fp16) = 24576

// ---- device-global scratch (no allocations allowed) ----
__device__ float g_hidden[(size_t)Bn * Hh];                       // stage A output
__device__ __align__(16) unsigned char g_Wq[TILES * WTILE_BYTES]; // stage B W fp16, tile-swizzled
__device__ __align__(16) unsigned char g_WA[Tt * 2 * WTILE_BYTES];// stage A W bank: phase0=Whh, 1=Wih

extern __shared__ __align__(1024) char dynsm[];

DEV float sigm(float v) { return 1.0f / (1.0f + __expf(-v)); }

DEV uint32_t smem_u32(const void* p) {
    uint32_t a;
    asm("{ .reg .u64 t; cvta.to.shared.u64 t, %1; cvt.u32.u64 %0, t; }" : "=r"(a) : "l"(p));
    return a;
}
DEV uint32_t sw128(uint32_t off) { return off ^ ((off >> 3) & 0x70); }

DEV void ldsm4(uint32_t* r, uint32_t addr) {
    asm volatile("ldmatrix.sync.aligned.m8n8.x4.shared.b16 {%0,%1,%2,%3}, [%4];"
        : "=r"(r[0]), "=r"(r[1]), "=r"(r[2]), "=r"(r[3]) : "r"(addr));
}
DEV void mma_f16(float* d, const uint32_t* a, const uint32_t* b) {
    asm volatile(
        "mma.sync.aligned.m16n8k16.row.col.f32.f16.f16.f32 "
        "{%0,%1,%2,%3}, {%4,%5,%6,%7}, {%8,%9}, {%0,%1,%2,%3};"
        : "+f"(d[0]), "+f"(d[1]), "+f"(d[2]), "+f"(d[3])
        : "r"(a[0]), "r"(a[1]), "r"(a[2]), "r"(a[3]), "r"(b[0]), "r"(b[1]));
}
DEV void cp16(uint32_t smem, const void* g) {
    asm volatile("cp.async.cg.shared.global [%0], [%1], 16;" :: "r"(smem), "l"(g));
}
DEV void cp_commit() { asm volatile("cp.async.commit_group;" ::: "memory"); }
DEV void cp_wait0()  { asm volatile("cp.async.wait_group 0;" ::: "memory"); }

DEV uint32_t packh2(float a, float b) {
    __half2 h = __floats2half2_rn(a, b);
    return *reinterpret_cast<uint32_t*>(&h);
}

// ---------------------------------------------------------------------------
// buildA / buildB: weights -> fp16 SW128 tiles (W loads become raw cp.async)
// ---------------------------------------------------------------------------
__global__ void buildA_kernel(const float* __restrict__ Wih, const float* __restrict__ Whh) {
    int idx = blockIdx.x * 256 + threadIdx.x;
    if (idx >= Tt * 2 * Gg * 64) return;
    int t   = idx / (2 * Gg * 64);
    int rem = idx - t * (2 * Gg * 64);
    int p   = rem / (Gg * 64);
    int r2  = rem - p * (Gg * 64);
    int r   = r2 >> 6;
    int kk  = r2 & 63;
    const float* src = (p == 0) ? Whh : Wih;
    float val = src[((size_t)t * Gg + r) * 64 + kk];
    uint32_t off = sw128((uint32_t)(r * 128 + kk * 2));
    *(__half*)(g_WA + (size_t)(t * 2 + p) * WTILE_BYTES + off) = __float2half_rn(val);
}

__global__ void buildB_kernel(const float* __restrict__ cWih, const float* __restrict__ cWhh) {
    int idx = blockIdx.x * 256 + threadIdx.x;
    if (idx >= TILES * Gg * 64) return;
    int t   = idx / (Gg * 64);
    int rem = idx - t * (Gg * 64);
    int r   = rem >> 6;
    int kk  = rem & 63;
    int k   = t * 64 + kk;
    float val = (k < Kf) ? cWih[(size_t)r * Kf + k] : cWhh[r * Hh + (k - Kf)];
    uint32_t off = sw128((uint32_t)(r * 128 + kk * 2));
    *(__half*)(g_Wq + (size_t)t * WTILE_BYTES + off) = __float2half_rn(val);
}

// ---------------------------------------------------------------------------
// Stage A (mma, single-pass fp16): per-(type, chunk) block.
// W0=Whh[t], W1=Wih[t] loaded ONCE per block. Per 64-row group:
// gather reg->A0, x->A1 (fp16), phase0 A0xW0 -> snapshot hn -> phase1 A1xW1,
// epilogue in two 32-row halves (Ds staging), reg reloaded fp32 from global.
// smem: W0@0 24K | W1@24576 24K | A0@49152 8K | A1@57344 8K |
//       HN@65536 16K | DS@81920 25600  -> 107520
// ---------------------------------------------------------------------------
constexpr int A_W0 = 0;
constexpr int A_W1 = 24576;
constexpr int A_A0 = 49152;
constexpr int A_A1 = 57344;
constexpr int A_HN = 65536;
constexpr int A_DS = 81920;
constexpr int SMEMA_BYTES = 107520;

__global__ void __launch_bounds__(256, 2)
stageA_mma(const float* __restrict__ x, const int* __restrict__ typ,
           const float* __restrict__ regs,
           const float* __restrict__ bih, const float* __restrict__ bhh)
{
    char* sm = dynsm;
    const uint32_t sb = smem_u32(sm);
    __shared__ int list[1024];
    __shared__ int pcnt;

    const int tid = threadIdx.x;
    const int wid = tid >> 5, lane = tid & 31;
    const int t   = blockIdx.y;
    const int c0  = blockIdx.x * 1024;

    if (tid == 0) pcnt = 0;
    __syncthreads();
    for (int i = tid; i < 1024; i += 256) {
        if (typ[c0 + i] == t) list[atomicAdd(&pcnt, 1)] = c0 + i;
    }
    __syncthreads();
    const int n = pcnt;
    if (n == 0) return;

    // hoisted W loads (once per block)
    {
        const unsigned char* w0 = g_WA + (size_t)(t * 2 + 0) * WTILE_BYTES;
        const unsigned char* w1 = g_WA + (size_t)(t * 2 + 1) * WTILE_BYTES;
        #pragma unroll
        for (int j = 0; j < 6; j++) {
            int i = (tid + j * 256) * 16;
            cp16(sb + A_W0 + i, w0 + i);
            cp16(sb + A_W1 + i, w1 + i);
        }
        cp_commit();
    }

    const int h  = tid & 63;
    const int rl = tid >> 6;
    const float bR  = bih[t * Gg + h]        + bhh[t * Gg + h];
    const float bZ  = bih[t * Gg + 64 + h]   + bhh[t * Gg + 64 + h];
    const float bN  = bih[t * Gg + 128 + h];
    const float bHN = bhh[t * Gg + 128 + h];

    const int arow = tid >> 2;      // gather: row 0..63
    const int aqd  = tid & 3;       // 16-float quarter

    const int l8 = lane & 7, li = lane >> 3;
    const int am_off = (li & 1) * 8, ak_off = (li >> 1) * 8;
    const int wn_off = (li >> 1) * 8, wk_off = (li & 1) * 8;
    const int wm = wid & 1;
    const int wn = wid >> 1;

    float* Hn = (float*)(sm + A_HN);
    float* Ds = (float*)(sm + A_DS);   // 32 rows x 200

    bool firstGroup = true;
    for (int base = 0; base < n; base += 64) {
        const int m = (n - base < 64) ? (n - base) : 64;

        int gj = base + arow; if (gj > n - 1) gj = n - 1;
        const int gb = list[gj];

        // gather reg -> A0, x -> A1 (fp16, swizzled)
        {
            const float* rrow = regs + (size_t)gb * Kf + t * 64;
            const float* xrow = x + (size_t)gb * 64;
            float fr[16], fx[16];
            #pragma unroll
            for (int i = 0; i < 4; i++) {
                float4 vr = *(const float4*)(rrow + aqd * 16 + i * 4);
                float4 vx = *(const float4*)(xrow + aqd * 16 + i * 4);
                fr[4*i] = vr.x; fr[4*i+1] = vr.y; fr[4*i+2] = vr.z; fr[4*i+3] = vr.w;
                fx[4*i] = vx.x; fx[4*i+1] = vx.y; fx[4*i+2] = vx.z; fx[4*i+3] = vx.w;
            }
            uint32_t hr[8], hx[8];
            #pragma unroll
            for (int i = 0; i < 8; i++) {
                hr[i] = packh2(fr[2*i], fr[2*i+1]);
                hx[i] = packh2(fx[2*i], fx[2*i+1]);
            }
            uint32_t bo = (uint32_t)(arow * 128 + aqd * 32);
            uint32_t o0 = sw128(bo), o1 = sw128(bo + 16);
            *(uint4*)(sm + A_A0 + o0) = make_uint4(hr[0], hr[1], hr[2], hr[3]);
            *(uint4*)(sm + A_A0 + o1) = make_uint4(hr[4], hr[5], hr[6], hr[7]);
            *(uint4*)(sm + A_A1 + o0) = make_uint4(hx[0], hx[1], hx[2], hx[3]);
            *(uint4*)(sm + A_A1 + o1) = make_uint4(hx[4], hx[5], hx[6], hx[7]);
        }
        if (firstGroup) { cp_wait0(); firstGroup = false; }
        __syncthreads();

        float acc[2][6][4];
        #pragma unroll
        for (int a = 0; a < 2; a++)
            #pragma unroll
            for (int b = 0; b < 6; b++)
                #pragma unroll
                for (int r = 0; r < 4; r++) acc[a][b][r] = 0.0f;

        // two phases: (A0,W0) then (A1,W1)
        #pragma unroll
        for (int ph = 0; ph < 2; ph++) {
            const uint32_t aB = sb + (ph ? A_A1 : A_A0);
            const uint32_t wB = sb + (ph ? A_W1 : A_W0);
            #pragma unroll
            for (int ks = 0; ks < 4; ks++) {
                const int k0 = ks * 16;
                uint32_t ah[2][4];
                #pragma unroll
                for (int mt = 0; mt < 2; mt++) {
                    int row = wm * 32 + mt * 16 + am_off + l8;
                    ldsm4(ah[mt], aB + sw128((uint32_t)(row * 128 + (k0 + ak_off) * 2)));
                }
                #pragma unroll
                for (int np = 0; np < 3; np++) {
                    int nrow = wn * 48 + np * 16 + wn_off + l8;
                    uint32_t wf[4];
                    ldsm4(wf, wB + sw128((uint32_t)(nrow * 128 + (k0 + wk_off) * 2)));
                    #pragma unroll
                    for (int mt = 0; mt < 2; mt++) {
                        mma_f16(acc[mt][2*np],   ah[mt], wf);
                        mma_f16(acc[mt][2*np+1], ah[mt], wf + 2);
                    }
                }
            }
            if (ph == 0) {
                // snapshot hn = reg @ Whh_n^T (cols 128..191)
                #pragma unroll
                for (int mt = 0; mt < 2; mt++)
                    #pragma unroll
                    for (int nt = 0; nt < 6; nt++) {
                        int colb = wn * 48 + nt * 8;
                        if (colb >= 128) {
                            #pragma unroll
                            for (int r = 0; r < 4; r++) {
                                int row = wm * 32 + mt * 16 + (lane >> 2) + ((r >> 1) << 3);
                                int col = colb - 128 + ((lane & 3) << 1) + (r & 1);
                                Hn[row * 64 + col] = acc[mt][nt][r];
                            }
                        }
                    }
            }
        }

        // epilogue in two 32-row halves
        #pragma unroll
        for (int half = 0; half < 2; half++) {
            __syncthreads();
            if (wm == half) {
                #pragma unroll
                for (int mt = 0; mt < 2; mt++)
                    #pragma unroll
                    for (int nt = 0; nt < 6; nt++)
                        #pragma unroll
                        for (int r = 0; r < 4; r++) {
                            int lrow = mt * 16 + (lane >> 2) + ((r >> 1) << 3);
                            int col  = wn * 48 + nt * 8 + ((lane & 3) << 1) + (r & 1);
                            Ds[lrow * 200 + col] = acc[mt][nt][r];
                        }
            }
            __syncthreads();
            #pragma unroll 2
            for (int i = 0; i < 8; i++) {
                int lrow = rl + i * 4;
                int rowg = half * 32 + lrow;
                if (rowg < m) {
                    int gbr = list[base + rowg];
                    float ar = Ds[lrow * 200 + h];
                    float az = Ds[lrow * 200 + 64 + h];
                    float an = Ds[lrow * 200 + 128 + h];
                    float hn = Hn[rowg * 64 + h];
                    float rg = regs[(size_t)gbr * Kf + t * 64 + h];
                    float rv = sigm(ar + bR);
                    float zv = sigm(az + bZ);
                    float nv = tanhf(an + bN + rv * bHN + (rv - 1.0f) * hn);
                    g_hidden[(size_t)gbr * 64 + h] = (1.0f - zv) * nv + zv * rg;
                }
            }
        }
        __syncthreads();   // A0/A1/Hn/Ds free before next group
    }
}

// ---------------------------------------------------------------------------
// Stage B: single-pass fp16 mma GEMM, 2-stage pipelined.
// Tile it=0 -> t=16 (c) for hn snapshot, then t=0..15.
// smem: stage buf = A 8K @ buf*32K | W 24K @ buf*32K+8K  (2 stages = 64K)
// epilogue overlay: Ds[64][200]@0 51200 | cs[64][68]@51200 | Hn@68608 16K
// ---------------------------------------------------------------------------
constexpr int SBUF  = 32768;
constexpr int SB_CS = 51200;
constexpr int SB_HN = 68608;
constexpr int SMEMB_BYTES = 84992;

__global__ void __launch_bounds__(256, 2)
stageB_mma(const float* __restrict__ regs, const int* __restrict__ typ,
           const float* __restrict__ c,
           const float* __restrict__ cbih, const float* __restrict__ cbhh,
           float* __restrict__ out)
{
    char* sm = dynsm;
    const uint32_t sb = smem_u32(sm);
    __shared__ int styp[64];

    const int tid  = threadIdx.x;
    const int wid  = tid >> 5, lane = tid & 31;
    const int wm   = wid & 1;
    const int wn   = wid >> 1;
    const int bm   = blockIdx.x * 64;

    if (tid < 64) styp[tid] = typ[bm + tid];
    __syncthreads();

    float acc[2][6][4];
    #pragma unroll
    for (int a = 0; a < 2; a++)
        #pragma unroll
        for (int b = 0; b < 6; b++)
            #pragma unroll
            for (int r = 0; r < 4; r++) acc[a][b][r] = 0.0f;

    const int arow = tid >> 2;
    const int aqd  = tid & 3;

    float4 pf[4];
    auto prefetchA = [&](int t) {
        const float* srow;
        if (t < Tt) {
            srow = (styp[arow] == t)
                     ? (g_hidden + (size_t)(bm + arow) * 64)
                     : (regs + (size_t)(bm + arow) * Kf + t * 64);
        } else {
            srow = c + (size_t)(bm + arow) * 64;
        }
        #pragma unroll
        for (int i = 0; i < 4; i++)
            pf[i] = *(const float4*)(srow + aqd * 16 + i * 4);
    };
    auto storeA = [&](int buf) {
        float f[16];
        #pragma unroll
        for (int i = 0; i < 4; i++) {
            f[4*i] = pf[i].x; f[4*i+1] = pf[i].y; f[4*i+2] = pf[i].z; f[4*i+3] = pf[i].w;
        }
        uint32_t hp[8];
        #pragma unroll
        for (int i = 0; i < 8; i++) hp[i] = packh2(f[2*i], f[2*i+1]);
        uint32_t bo = (uint32_t)(arow * 128 + aqd * 32);
        uint32_t o0 = sw128(bo), o1 = sw128(bo + 16);
        *(uint4*)(sm + buf * SBUF + o0) = make_uint4(hp[0], hp[1], hp[2], hp[3]);
        *(uint4*)(sm + buf * SBUF + o1) = make_uint4(hp[4], hp[5], hp[6], hp[7]);
    };
    auto loadW = [&](int t, int buf) {
        const unsigned char* src = g_Wq + (size_t)t * WTILE_BYTES;
        #pragma unroll
        for (int j = 0; j < 6; j++) {
            int i = (tid + j * 256) * 16;
            cp16(sb + buf * SBUF + 8192 + i, src + i);
        }
    };

    const int l8 = lane & 7, li = lane >> 3;
    const int am_off = (li & 1) * 8, ak_off = (li >> 1) * 8;
    const int wn_off = (li >> 1) * 8, wk_off = (li & 1) * 8;

    // prologue: tile it=0 (t=16, the c tile) into buf 0
    prefetchA(16);
    loadW(16, 0);
    cp_commit();
    storeA(0);
    prefetchA(0);
    cp_wait0();
    __syncthreads();

    for (int it = 0; it <= 16; it++) {
        const int buf = it & 1, nxt = buf ^ 1;
        if (it < 16) {
            loadW(it, nxt);
            cp_commit();
            storeA(nxt);                 // pf holds A for t = it (iteration it+1)
            if (it < 15) prefetchA(it + 1);
        }

        const uint32_t aB = sb + buf * SBUF;
        const uint32_t wB = aB + 8192;
        #pragma unroll
        for (int ks = 0; ks < 4; ks++) {
            const int k0 = ks * 16;
            uint32_t ah[2][4];
            #pragma unroll
            for (int mt = 0; mt < 2; mt++) {
                int row = wm * 32 + mt * 16 + am_off + l8;
                ldsm4(ah[mt], aB + sw128((uint32_t)(row * 128 + (k0 + ak_off) * 2)));
            }
            #pragma unroll
            for (int np = 0; np < 3; np++) {
                int nrow = wn * 48 + np * 16 + wn_off + l8;
                uint32_t wf[4];
                ldsm4(wf, wB + sw128((uint32_t)(nrow * 128 + (k0 + wk_off) * 2)));
                #pragma unroll
                for (int mt = 0; mt < 2; mt++) {
                    mma_f16(acc[mt][2*np],   ah[mt], wf);
                    mma_f16(acc[mt][2*np+1], ah[mt], wf + 2);
                }
            }
        }

        if (it == 0) {
            float* Hn = (float*)(sm + SB_HN);
            #pragma unroll
            for (int mt = 0; mt < 2; mt++)
                #pragma unroll
                for (int nt = 0; nt < 6; nt++) {
                    int colb = wn * 48 + nt * 8;
                    if (colb >= 128) {
                        #pragma unroll
                        for (int r = 0; r < 4; r++) {
                            int row = wm * 32 + mt * 16 + (lane >> 2) + ((r >> 1) << 3);
                            int col = colb - 128 + ((lane & 3) << 1) + (r & 1);
                            Hn[row * 64 + col] = acc[mt][nt][r];
                        }
                    }
                }
        }
        cp_wait0();
        __syncthreads();
    }

    // ---- epilogue ----
    float* Ds = (float*)sm;               // [64][200]
    float* cs = (float*)(sm + SB_CS);     // [64][68]
    float* Hn = (float*)(sm + SB_HN);     // [64][64]

    #pragma unroll
    for (int mt = 0; mt < 2; mt++)
        #pragma unroll
        for (int nt = 0; nt < 6; nt++)
            #pragma unroll
            for (int r = 0; r < 4; r++) {
                int row = wm * 32 + mt * 16 + (lane >> 2) + ((r >> 1) << 3);
                int col = wn * 48 + nt * 8 + ((lane & 3) << 1) + (r & 1);
                Ds[row * 200 + col] = acc[mt][nt][r];
            }
    #pragma unroll
    for (int j = 0; j < 4; j++) {
        int i   = tid + j * 256;
        int row = i >> 4, q = i & 15;
        float4 v = *(const float4*)(c + (size_t)(bm + row) * 64 + q * 4);
        *(float4*)(cs + row * 68 + q * 4) = v;
    }
    __syncthreads();

    const int h  = tid & 63;
    const int rl = tid >> 6;
    const float bR  = cbih[h]       + cbhh[h];
    const float bZ  = cbih[64 + h]  + cbhh[64 + h];
    const float bN  = cbih[128 + h];
    const float bHN = cbhh[128 + h];
    #pragma unroll 4
    for (int i = 0; i < 16; i++) {
        int row = rl + i * 4;
        float ar = Ds[row * 200 + h];
        float az = Ds[row * 200 + 64 + h];
        float an = Ds[row * 200 + 128 + h];
        float hn = Hn[row * 64 + h];
        float cv = cs[row * 68 + h];
        float rv = sigm(ar + bR);
        float zv = sigm(az + bZ);
        float nv = tanhf(an + bN + rv * bHN + (rv - 1.0f) * hn);
        out[(size_t)(bm + row) * 64 + h] = (1.0f - zv) * nv + zv * cv;
    }
}

// ---------------------------------------------------------------------------
extern "C" void kernel_launch(void* const* d_in, const int* in_sizes, int n_in,
                              void* d_out, int out_size)
{
    const float* x    = (const float*)d_in[0];
    const int*   typ  = (const int*)  d_in[1];
    const float* c    = (const float*)d_in[2];
    const float* regs = (const float*)d_in[3];
    const float* Wih  = (const float*)d_in[4];
    const float* Whh  = (const float*)d_in[5];
    const float* bih  = (const float*)d_in[6];
    const float* bhh  = (const float*)d_in[7];
    const float* cWih = (const float*)d_in[8];
    const float* cWhh = (const float*)d_in[9];
    const float* cbih = (const float*)d_in[10];
    const float* cbhh = (const float*)d_in[11];
    float* out = (float*)d_out;

    (void)in_sizes; (void)n_in; (void)out_size;

    cudaFuncSetAttribute(stageA_mma,
                         cudaFuncAttributeMaxDynamicSharedMemorySize, SMEMA_BYTES);
    cudaFuncSetAttribute(stageB_mma,
                         cudaFuncAttributeMaxDynamicSharedMemorySize, SMEMB_BYTES);

    buildA_kernel<<<(Tt * 2 * Gg * 64 + 255) / 256, 256>>>(Wih, Whh);
    stageA_mma<<<dim3(64, 16), 256, SMEMA_BYTES>>>(x, typ, regs, bih, bhh);
    buildB_kernel<<<(TILES * Gg * 64 + 255) / 256, 256>>>(cWih, cWhh);
    stageB_mma<<<Bn / 64, 256, SMEMB_BYTES>>>(regs, typ, c, cbih, cbhh, out);
}